// round 3
// baseline (speedup 1.0000x reference)
#include <cuda_runtime.h>
#include <math_constants.h>

// Problem constants (from reference setup_inputs)
constexpr int B = 32;
constexpr int F = 1024;
constexpr int S = 2048;
constexpr int K = 16;

constexpr int RC = 16;                      // row chunks per b
constexpr int ROWS_PER_CHUNK = S / RC;      // 128
constexpr int COLS_PER_BLOCK = 1024;        // 256 threads * float4
constexpr int CCHUNKS = S / COLS_PER_BLOCK; // 2

// Scratch (no allocations allowed in kernel_launch)
__device__ float g_partial[(size_t)B * RC * S];   // 4 MiB
__device__ int   g_idx[B * K];

// ---------------------------------------------------------------------------
// Kernel 1: partial column sums of w over row chunks.
// Block = (b, row_chunk, col_chunk). 256 threads, each owns 4 contiguous
// columns (float4). Fully coalesced streaming reads; deterministic
// (fixed per-thread accumulation order, no atomics).
// ---------------------------------------------------------------------------
__global__ __launch_bounds__(256) void colsum_partial_kernel(const float* __restrict__ w) {
    int blk = blockIdx.x;
    int cc = blk & (CCHUNKS - 1);
    int rc = (blk >> 1) & (RC - 1);
    int b  = blk >> 5;                       // /(RC*CCHUNKS)=32

    const float4* __restrict__ base = reinterpret_cast<const float4*>(
        w + (size_t)b * S * S + (size_t)rc * ROWS_PER_CHUNK * S + cc * COLS_PER_BLOCK);

    int t = threadIdx.x;
    float4 acc = make_float4(0.f, 0.f, 0.f, 0.f);

    // 128 rows; unroll to front-batch independent LDG.128s (MLP for DRAM)
    #pragma unroll 8
    for (int r = 0; r < ROWS_PER_CHUNK; ++r) {
        float4 v = base[(size_t)r * (S / 4) + t];
        acc.x += v.x; acc.y += v.y; acc.z += v.z; acc.w += v.w;
    }

    float4* __restrict__ out = reinterpret_cast<float4*>(
        g_partial + ((size_t)b * RC + rc) * S + cc * COLS_PER_BLOCK);
    out[t] = acc;
}

// ---------------------------------------------------------------------------
// Kernel 2: per-b reduce of partials + iterative top-16 argmax.
// One block per b. Tie-break: smaller index wins (matches lax.top_k).
// Emits indices in descending-value order (output ordering depends on it).
// ---------------------------------------------------------------------------
__global__ __launch_bounds__(256) void reduce_topk_kernel() {
    int b = blockIdx.x;
    int t = threadIdx.x;

    __shared__ float vals[S];
    __shared__ float redv[256];
    __shared__ int   redi[256];

    // Deterministic reduce over the 16 row-chunk partials
    for (int s = t; s < S; s += 256) {
        float acc = 0.f;
        #pragma unroll
        for (int rc = 0; rc < RC; ++rc)
            acc += g_partial[((size_t)b * RC + rc) * S + s];
        vals[s] = acc;
    }
    __syncthreads();

    for (int k = 0; k < K; ++k) {
        float best = -CUDART_INF_F;
        int bi = S;
        for (int s = t; s < S; s += 256) {
            float v = vals[s];
            if (v > best || (v == best && s < bi)) { best = v; bi = s; }
        }
        redv[t] = best; redi[t] = bi;
        __syncthreads();
        for (int off = 128; off > 0; off >>= 1) {
            if (t < off) {
                float v = redv[t + off]; int i = redi[t + off];
                if (v > redv[t] || (v == redv[t] && i < redi[t])) {
                    redv[t] = v; redi[t] = i;
                }
            }
            __syncthreads();
        }
        if (t == 0) {
            g_idx[b * K + k] = redi[0];
            vals[redi[0]] = -CUDART_INF_F;   // knock out for next iteration
        }
        __syncthreads();
    }
}

// ---------------------------------------------------------------------------
// Kernel 3: gather out[b,f,k] = x[b,f,idx[b,k]]. Coalesced writes; reads are
// scattered columns but total traffic is tiny (~16 MiB of sectors).
// ---------------------------------------------------------------------------
__global__ __launch_bounds__(256) void gather_kernel(const float* __restrict__ x,
                                                     float* __restrict__ out) {
    int i = blockIdx.x * blockDim.x + threadIdx.x;   // over B*F*K = 524288
    int k = i & (K - 1);
    int f = (i / K) & (F - 1);
    int b = i / (K * F);
    int s = g_idx[b * K + k];
    out[i] = x[((size_t)(b * F + f)) * S + s];
}

extern "C" void kernel_launch(void* const* d_in, const int* in_sizes, int n_in,
                              void* d_out, int out_size) {
    const float* x = (const float*)d_in[0];   // [B, F, S]
    const float* w = (const float*)d_in[1];   // [B, S, S]
    float* out = (float*)d_out;               // [B, F, K]

    colsum_partial_kernel<<<B * RC * CCHUNKS, 256>>>(w);
    reduce_topk_kernel<<<B, 256>>>();
    gather_kernel<<<(B * F * K) / 256, 256>>>(x, out);
}

// round 4
// speedup vs baseline: 1.0536x; 1.0536x over previous
#include <cuda_runtime.h>
#include <math_constants.h>

// Problem constants (from reference setup_inputs)
constexpr int B = 32;
constexpr int F = 1024;
constexpr int S = 2048;
constexpr int K = 16;

constexpr int RC = 16;                      // row chunks per b
constexpr int ROWS_PER_CHUNK = S / RC;      // 128
constexpr int COLS_PER_BLOCK = 1024;        // 256 threads * float4
constexpr int CCHUNKS = S / COLS_PER_BLOCK; // 2
constexpr int BLOCKS_PER_B = RC * CCHUNKS;  // 32

// Scratch (no allocations allowed anywhere)
__device__ float g_partial[(size_t)B * RC * S];   // 4 MiB
__device__ int   g_idx[B * K];
__device__ int   g_done[B];                        // zero-init; self-resets each run

// ---------------------------------------------------------------------------
// Kernel 1: partial column sums of w + fused per-b top-16.
// Each block: (b, row_chunk, col_chunk), 256 threads, float4 per thread.
// The last block to finish for a given b (atomic counter) sums the 16
// partials (L2-hot) and runs an iterative warp-shuffle top-16 argmax.
// Tie-break: smaller index wins (matches lax.top_k); indices emitted in
// descending-value order (output ordering depends on it). Deterministic:
// fixed accumulation order, no float atomics.
// ---------------------------------------------------------------------------
__global__ __launch_bounds__(256) void colsum_topk_kernel(const float* __restrict__ w) {
    int blk = blockIdx.x;
    int cc = blk & (CCHUNKS - 1);
    int rc = (blk >> 1) & (RC - 1);
    int b  = blk >> 5;                       // / BLOCKS_PER_B
    int t  = threadIdx.x;

    // ---- streaming column partial-sum (the 512 MiB, HBM-bound part) ----
    const float4* __restrict__ base = reinterpret_cast<const float4*>(
        w + (size_t)b * S * S + (size_t)rc * ROWS_PER_CHUNK * S + cc * COLS_PER_BLOCK);

    float4 acc = make_float4(0.f, 0.f, 0.f, 0.f);
    #pragma unroll 8
    for (int r = 0; r < ROWS_PER_CHUNK; ++r) {
        float4 v = base[(size_t)r * (S / 4) + t];
        acc.x += v.x; acc.y += v.y; acc.z += v.z; acc.w += v.w;
    }
    reinterpret_cast<float4*>(
        g_partial + ((size_t)b * RC + rc) * S + cc * COLS_PER_BLOCK)[t] = acc;

    // ---- last-block-per-b election ----
    __shared__ int s_last;
    __syncthreads();
    if (t == 0) {
        __threadfence();                                   // publish partials
        int old = atomicAdd(&g_done[b], 1);
        s_last = (old == BLOCKS_PER_B - 1);
    }
    __syncthreads();
    if (!s_last) return;
    __threadfence();                                       // acquire partials

    // ---- reduce 16 partials -> vals[2048] in shared ----
    __shared__ float vals[S];                              // 8 KB
    __shared__ float wv[8];
    __shared__ int   wi[8];
    for (int s = t; s < S; s += 256) {
        float a = 0.f;
        #pragma unroll
        for (int r = 0; r < RC; ++r)
            a += g_partial[((size_t)b * RC + r) * S + s];
        vals[s] = a;
    }
    __syncthreads();

    // ---- iterative top-16 argmax (warp shuffles, 2 barriers/iter) ----
    int lane = t & 31, warp = t >> 5;
    for (int k = 0; k < K; ++k) {
        float best = -CUDART_INF_F;
        int bi = S;
        #pragma unroll
        for (int j = 0; j < S / 256; ++j) {
            int s = t + j * 256;
            float v = vals[s];
            if (v > best || (v == best && s < bi)) { best = v; bi = s; }
        }
        #pragma unroll
        for (int off = 16; off > 0; off >>= 1) {
            float ov = __shfl_xor_sync(0xFFFFFFFFu, best, off);
            int   oi = __shfl_xor_sync(0xFFFFFFFFu, bi,   off);
            if (ov > best || (ov == best && oi < bi)) { best = ov; bi = oi; }
        }
        if (lane == 0) { wv[warp] = best; wi[warp] = bi; }
        __syncthreads();
        if (t == 0) {
            float bb = wv[0]; int ii = wi[0];
            #pragma unroll
            for (int wdx = 1; wdx < 8; ++wdx) {
                if (wv[wdx] > bb || (wv[wdx] == bb && wi[wdx] < ii)) {
                    bb = wv[wdx]; ii = wi[wdx];
                }
            }
            g_idx[b * K + k] = ii;
            vals[ii] = -CUDART_INF_F;                      // knockout
        }
        __syncthreads();
    }

    if (t == 0) g_done[b] = 0;                             // reset for graph replay
}

// ---------------------------------------------------------------------------
// Kernel 2: gather out[b,f,k] = x[b,f,idx[b,k]]. Coalesced writes; reads are
// inherently scattered columns (~16 MiB of sectors total).
// ---------------------------------------------------------------------------
__global__ __launch_bounds__(256) void gather_kernel(const float* __restrict__ x,
                                                     float* __restrict__ out) {
    int i = blockIdx.x * blockDim.x + threadIdx.x;   // over B*F*K = 524288
    int k = i & (K - 1);
    int f = (i / K) & (F - 1);
    int b = i / (K * F);
    int s = g_idx[b * K + k];
    out[i] = x[((size_t)(b * F + f)) * S + s];
}

extern "C" void kernel_launch(void* const* d_in, const int* in_sizes, int n_in,
                              void* d_out, int out_size) {
    const float* x = (const float*)d_in[0];   // [B, F, S]
    const float* w = (const float*)d_in[1];   // [B, S, S]
    float* out = (float*)d_out;               // [B, F, K]

    colsum_topk_kernel<<<B * BLOCKS_PER_B, 256>>>(w);
    gather_kernel<<<(B * F * K) / 256, 256>>>(x, out);
}

// round 7
// speedup vs baseline: 1.0949x; 1.0392x over previous
#include <cuda_runtime.h>
#include <math_constants.h>

// Problem constants (from reference setup_inputs)
constexpr int B = 32;
constexpr int F = 1024;
constexpr int S = 2048;
constexpr int K = 16;

constexpr int RC = 16;                      // row chunks per b
constexpr int ROWS_PER_CHUNK = S / RC;      // 128
constexpr int COLS_PER_BLOCK = 1024;        // 256 threads * float4
constexpr int CCHUNKS = S / COLS_PER_BLOCK; // 2
constexpr int BLOCKS_PER_B = RC * CCHUNKS;  // 32

// Scratch (no allocations allowed anywhere). All counters/flags self-reset.
__device__ float g_partial[(size_t)B * RC * S];   // 4 MiB
__device__ int   g_idx[B * K];
__device__ int   g_done[B];                       // colsum-arrival counter
__device__ int   g_ready[B];                      // topk-published flag
__device__ int   g_done2[B];                      // gather-arrival counter

// ---------------------------------------------------------------------------
// Single fused kernel:
//   phase 1: streaming column partial-sums of w (HBM-bound, 512 MiB)
//   phase 2: last block per b reduces partials + iterative top-16 argmax
//   phase 3: ALL 32 blocks of b gather their slice of out[b,:,:] — this
//            overlaps with other batches' phase-1 streaming, hiding the
//            scatter-gather's DRAM latency/amplification under the stream.
// __launch_bounds__(256,8) forces <=32 regs so the whole 1024-block grid is
// co-resident (8 blocks/SM * 148 SMs = 1184) -> the per-b spin cannot
// deadlock. Deterministic: fixed accumulation order, no float atomics.
// Tie-break: smaller index wins; indices emitted in descending-value order
// (matches lax.top_k, and the output ordering depends on it).
// ---------------------------------------------------------------------------
__global__ __launch_bounds__(256, 8) void fused_kernel(const float* __restrict__ w,
                                                       const float* __restrict__ x,
                                                       float* __restrict__ out) {
    int blk = blockIdx.x;
    int cc = blk & (CCHUNKS - 1);
    int rc = (blk >> 1) & (RC - 1);
    int b  = blk >> 5;                       // / BLOCKS_PER_B
    int local = blk & (BLOCKS_PER_B - 1);    // 0..31 within b
    int t  = threadIdx.x;

    // ---- phase 1: streaming column partial-sum ----
    const float4* __restrict__ base = reinterpret_cast<const float4*>(
        w + (size_t)b * S * S + (size_t)rc * ROWS_PER_CHUNK * S + cc * COLS_PER_BLOCK);

    float4 acc = make_float4(0.f, 0.f, 0.f, 0.f);
    #pragma unroll 8
    for (int r = 0; r < ROWS_PER_CHUNK; ++r) {
        float4 v = base[(size_t)r * (S / 4) + t];
        acc.x += v.x; acc.y += v.y; acc.z += v.z; acc.w += v.w;
    }
    reinterpret_cast<float4*>(
        g_partial + ((size_t)b * RC + rc) * S + cc * COLS_PER_BLOCK)[t] = acc;

    // ---- last-block-per-b election ----
    __shared__ int s_last;
    __syncthreads();
    if (t == 0) {
        __threadfence();                                   // publish partials
        int old = atomicAdd(&g_done[b], 1);
        s_last = (old == BLOCKS_PER_B - 1);
    }
    __syncthreads();

    if (s_last) {
        __threadfence();                                   // acquire partials

        // ---- phase 2: reduce 16 partials -> vals[2048], then top-16 ----
        __shared__ float vals[S];                          // 8 KB
        __shared__ float wv[8];
        __shared__ int   wi[8];
        for (int s = t; s < S; s += 256) {
            float a = 0.f;
            #pragma unroll
            for (int r = 0; r < RC; ++r)
                a += g_partial[((size_t)b * RC + r) * S + s];
            vals[s] = a;
        }
        __syncthreads();

        int lane = t & 31, warp = t >> 5;
        for (int k = 0; k < K; ++k) {
            float best = -CUDART_INF_F;
            int bi = S;
            #pragma unroll
            for (int j = 0; j < S / 256; ++j) {
                int s = t + j * 256;
                float v = vals[s];
                if (v > best || (v == best && s < bi)) { best = v; bi = s; }
            }
            #pragma unroll
            for (int off = 16; off > 0; off >>= 1) {
                float ov = __shfl_xor_sync(0xFFFFFFFFu, best, off);
                int   oi = __shfl_xor_sync(0xFFFFFFFFu, bi,   off);
                if (ov > best || (ov == best && oi < bi)) { best = ov; bi = oi; }
            }
            if (lane == 0) { wv[warp] = best; wi[warp] = bi; }
            __syncthreads();
            if (t == 0) {
                float bb = wv[0]; int ii = wi[0];
                #pragma unroll
                for (int wdx = 1; wdx < 8; ++wdx) {
                    if (wv[wdx] > bb || (wv[wdx] == bb && wi[wdx] < ii)) {
                        bb = wv[wdx]; ii = wi[wdx];
                    }
                }
                g_idx[b * K + k] = ii;
                vals[ii] = -CUDART_INF_F;                  // knockout
            }
            __syncthreads();
        }
        if (t == 0) {
            __threadfence();                               // publish g_idx
            atomicExch(&g_ready[b], 1);
        }
    }

    // ---- wait for this b's indices (short spin; whole grid is resident) ----
    if (t == 0) {
        while (atomicAdd(&g_ready[b], 0) == 0) __nanosleep(200);
    }
    __syncthreads();
    __threadfence();                                       // acquire g_idx

    // ---- phase 3: gather this block's 1/32 slice of out[b,:,:] ----
    __shared__ int s_idx[K];
    if (t < K) s_idx[t] = g_idx[b * K + t];
    __syncthreads();

    // 512 elements per block = 128 float4 stores; t<128 each does 4 scattered
    // loads (good MLP) and one coalesced 16B store.
    if (t < 128) {
        int f  = local * 32 + (t >> 2);                    // 0..1023
        int kq = (t & 3) * 4;                              // k quad base
        const float* __restrict__ xrow = x + ((size_t)(b * F + f)) * S;
        float4 o;
        o.x = xrow[s_idx[kq + 0]];
        o.y = xrow[s_idx[kq + 1]];
        o.z = xrow[s_idx[kq + 2]];
        o.w = xrow[s_idx[kq + 3]];
        reinterpret_cast<float4*>(out + ((size_t)(b * F + f)) * K)[t & 3] = o;
    }

    // ---- self-reset for graph replay (last block of b to finish gather) ----
    __syncthreads();
    if (t == 0) {
        int old2 = atomicAdd(&g_done2[b], 1);
        if (old2 == BLOCKS_PER_B - 1) {
            g_done[b]  = 0;
            g_ready[b] = 0;
            g_done2[b] = 0;
        }
    }
}

extern "C" void kernel_launch(void* const* d_in, const int* in_sizes, int n_in,
                              void* d_out, int out_size) {
    const float* x = (const float*)d_in[0];   // [B, F, S]
    const float* w = (const float*)d_in[1];   // [B, S, S]
    float* out = (float*)d_out;               // [B, F, K]

    fused_kernel<<<B * BLOCKS_PER_B, 256>>>(w, x, out);
}